// round 6
// baseline (speedup 1.0000x reference)
#include <cuda_runtime.h>
#include <math.h>

// ---------------- problem constants ----------------
#define T_STEPS 512
#define BATCH   256
#define FIN     64
#define HID     256
#define G3      768
#define ROWS_TOT (T_STEPS*BATCH)   // 131072

// recurrent kernel partitioning
#define R_GRID    128        // 8 batch tiles x 16 hidden tiles
#define R_THREADS 256
#define RB        32         // batch rows per CTA
#define WSTRIDE   258        // padded K stride for weight smem rows
#define GSTRIDE   49         // padded stride for gate result tiles

// dynamic smem floats: 3 weight slices + 2 input tiles + 2 gate tiles
#define R_SMEM_FLOATS (3*48*WSTRIDE + 2*RB*HID + 2*RB*GSTRIDE)
#define R_SMEM_BYTES  (R_SMEM_FLOATS*4)

// ---------------- device scratch (static: no allocs allowed) ----------------
// g_feats doubles as the value-net hidden buffer (feats is dead after gi0).
__device__ float g_feats [(size_t)ROWS_TOT*HID];   // 134 MB (reused as v-hidden)
__device__ float g_gi0   [(size_t)ROWS_TOT*G3];    // 402 MB (layer0 gi incl b_ih0)
__device__ float g_gruout[(size_t)ROWS_TOT*HID];   // 134 MB
__device__ float g_hbuf  [2][2][BATCH][HID];       // [parity][layer][B][H] ping-pong
__device__ unsigned g_bar;

// ---------------- helpers ----------------
__device__ __forceinline__ float2 ffma2(float2 a, float2 b, float2 c) {
    unsigned long long au = *reinterpret_cast<unsigned long long*>(&a);
    unsigned long long bu = *reinterpret_cast<unsigned long long*>(&b);
    unsigned long long cu = *reinterpret_cast<unsigned long long*>(&c);
    unsigned long long du;
    asm("fma.rn.f32x2 %0, %1, %2, %3;" : "=l"(du) : "l"(au), "l"(bu), "l"(cu));
    return *reinterpret_cast<float2*>(&du);
}

__device__ __forceinline__ float sigmoidf_(float x) { return 1.0f / (1.0f + __expf(-x)); }

// local weight-row (0..47) -> global gate row for hidden base hb
__device__ __forceinline__ int grow_map(int hb, int c) {
    return (c < 16) ? (hb + c) : (c < 32) ? (256 + hb + (c - 16)) : (512 + hb + (c - 32));
}

__global__ void init_bar_kernel() { g_bar = 0u; }

// ---------------- generic tiled fp32 GEMM: C = act(A[M,K] @ W[N,K]^T + bias) ----------------
// BM=64, BN=64, BK=16, 128 threads, per-thread 8 rows x 4 cols (row-paired f32x2 accums)
template <bool LRELU>
__global__ void __launch_bounds__(128) gemm_lin_kernel(
    const float* __restrict__ A, const float* __restrict__ W,
    const float* __restrict__ bias, float* __restrict__ C,
    int M, int N, int K)
{
    __shared__ __align__(16) float As[16][68];
    __shared__ __align__(16) float Bs[16][68];

    const int tid  = threadIdx.x;
    const int row0 = blockIdx.y * 64;
    const int col0 = blockIdx.x * 64;
    const int c0 = (tid & 15) * 4;   // 4 cols
    const int r0 = (tid >> 4) * 8;   // 8 rows

    float2 acc[4][4];
#pragma unroll
    for (int i = 0; i < 4; i++)
#pragma unroll
        for (int j = 0; j < 4; j++) acc[i][j] = make_float2(0.f, 0.f);

    for (int kt = 0; kt < K; kt += 16) {
#pragma unroll
        for (int i = 0; i < 2; i++) {
            int e  = tid + i * 128;         // 0..255
            int r  = e >> 2;                // 0..63
            int k4 = (e & 3) * 4;           // 0,4,8,12
            float4 va = *(const float4*)&A[(size_t)(row0 + r) * K + kt + k4];
            As[k4 + 0][r] = va.x; As[k4 + 1][r] = va.y; As[k4 + 2][r] = va.z; As[k4 + 3][r] = va.w;
            float4 vb = *(const float4*)&W[(size_t)(col0 + r) * K + kt + k4];
            Bs[k4 + 0][r] = vb.x; Bs[k4 + 1][r] = vb.y; Bs[k4 + 2][r] = vb.z; Bs[k4 + 3][r] = vb.w;
        }
        __syncthreads();
#pragma unroll
        for (int k = 0; k < 16; k++) {
            float4 a03 = *(const float4*)&As[k][r0];
            float4 a47 = *(const float4*)&As[k][r0 + 4];
            float4 b   = *(const float4*)&Bs[k][c0];
            float2 ap[4] = { make_float2(a03.x, a03.y), make_float2(a03.z, a03.w),
                             make_float2(a47.x, a47.y), make_float2(a47.z, a47.w) };
            float2 bd[4] = { make_float2(b.x, b.x), make_float2(b.y, b.y),
                             make_float2(b.z, b.z), make_float2(b.w, b.w) };
#pragma unroll
            for (int i = 0; i < 4; i++)
#pragma unroll
                for (int j = 0; j < 4; j++) acc[i][j] = ffma2(ap[i], bd[j], acc[i][j]);
        }
        __syncthreads();
    }

#pragma unroll
    for (int j = 0; j < 4; j++) {
        float bv = bias[col0 + c0 + j];
#pragma unroll
        for (int i = 0; i < 4; i++) {
            float v0 = acc[i][j].x + bv;
            float v1 = acc[i][j].y + bv;
            if (LRELU) { v0 = (v0 > 0.f) ? v0 : 0.01f * v0; v1 = (v1 > 0.f) ? v1 : 0.01f * v1; }
            C[(size_t)(row0 + r0 + 2 * i    ) * N + col0 + c0 + j] = v0;
            C[(size_t)(row0 + r0 + 2 * i + 1) * N + col0 + c0 + j] = v1;
        }
    }
}

// ---------------- recurrent tile GEMM: out[32][48] = in[32][256] @ w[48][256]^T + bias ----------------
__device__ __forceinline__ void gemm_tile(const float* __restrict__ in_s,
                                          const float* __restrict__ w_s,
                                          float* __restrict__ out_s,
                                          const float* __restrict__ bias_g,
                                          int hb, int tid)
{
    const int ctl = tid & 15;
    const int rtl = tid >> 4;       // 0..15
    const int c0 = ctl * 3;         // 3 cols
    const int r0 = rtl * 2;         // 2 rows

    float2 a00 = make_float2(0.f, 0.f), a01 = a00, a02 = a00;
    float2 a10 = a00, a11 = a00, a12 = a00;

    const float* i0 = in_s + (size_t)r0 * HID;
    const float* i1 = in_s + (size_t)(r0 + 1) * HID;
    const float* w0 = w_s + (size_t)(c0 + 0) * WSTRIDE;
    const float* w1 = w_s + (size_t)(c0 + 1) * WSTRIDE;
    const float* w2 = w_s + (size_t)(c0 + 2) * WSTRIDE;

#pragma unroll 8
    for (int k = 0; k < HID; k += 2) {
        float2 x0 = *(const float2*)(i0 + k);
        float2 x1 = *(const float2*)(i1 + k);
        float2 b0 = *(const float2*)(w0 + k);
        float2 b1 = *(const float2*)(w1 + k);
        float2 b2 = *(const float2*)(w2 + k);
        a00 = ffma2(x0, b0, a00); a01 = ffma2(x0, b1, a01); a02 = ffma2(x0, b2, a02);
        a10 = ffma2(x1, b0, a10); a11 = ffma2(x1, b1, a11); a12 = ffma2(x1, b2, a12);
    }
    float bb0 = __ldg(&bias_g[grow_map(hb, c0 + 0)]);
    float bb1 = __ldg(&bias_g[grow_map(hb, c0 + 1)]);
    float bb2 = __ldg(&bias_g[grow_map(hb, c0 + 2)]);
    out_s[(r0    ) * GSTRIDE + c0 + 0] = a00.x + a00.y + bb0;
    out_s[(r0    ) * GSTRIDE + c0 + 1] = a01.x + a01.y + bb1;
    out_s[(r0    ) * GSTRIDE + c0 + 2] = a02.x + a02.y + bb2;
    out_s[(r0 + 1) * GSTRIDE + c0 + 0] = a10.x + a10.y + bb0;
    out_s[(r0 + 1) * GSTRIDE + c0 + 1] = a11.x + a11.y + bb1;
    out_s[(r0 + 1) * GSTRIDE + c0 + 2] = a12.x + a12.y + bb2;
}

// ---------------- persistent recurrent kernel ----------------
// blk = bt*16 + ct ; bt = batch tile (32 rows), ct = hidden tile (16 units -> 48 gate rows)
__global__ void __launch_bounds__(R_THREADS, 1) recurrent_kernel(
    const int*   __restrict__ dones,
    const float* __restrict__ w_ih,   // [2][768][256]
    const float* __restrict__ w_hh,   // [2][768][256]
    const float* __restrict__ b_ih,   // [2][768]
    const float* __restrict__ b_hh)   // [2][768]
{
    extern __shared__ __align__(16) float smem[];
    float* w0s = smem;                       // w_hh0 slice [48][WSTRIDE]
    float* w1s = w0s + 48 * WSTRIDE;         // w_ih1 slice
    float* w2s = w1s + 48 * WSTRIDE;         // w_hh1 slice
    float* inA = w2s + 48 * WSTRIDE;         // [32][256]
    float* inB = inA + RB * HID;             // [32][256]
    float* outA = inB + RB * HID;            // [32][GSTRIDE]
    float* outB = outA + RB * GSTRIDE;       // [32][GSTRIDE]
    __shared__ float smask[RB];

    const int tid = threadIdx.x;
    const int bt  = blockIdx.x >> 4;
    const int ct  = blockIdx.x & 15;
    const int b0  = bt * RB;
    const int hb  = ct * 16;

    const float* w_hh0 = w_hh;
    const float* w_ih1 = w_ih + 768 * 256;
    const float* w_hh1 = w_hh + 768 * 256;
    const float* b_hh0 = b_hh;
    const float* b_ih1 = b_ih + 768;
    const float* b_hh1 = b_hh + 768;

    // ---- load persistent weight slices (resident in smem for all 512 steps) ----
    for (int idx = tid; idx < 48 * HID; idx += R_THREADS) {
        int c = idx >> 8, k = idx & 255;
        int gr = grow_map(hb, c);
        w0s[c * WSTRIDE + k] = w_hh0[gr * HID + k];
        w1s[c * WSTRIDE + k] = w_ih1[gr * HID + k];
        w2s[c * WSTRIDE + k] = w_hh1[gr * HID + k];
    }
    __syncthreads();

    for (int t = 0; t < T_STEPS; t++) {
        const int rp = t & 1, wp = rp ^ 1;

        // ---- done masks for this step ----
        if (tid < RB) smask[tid] = 1.0f - (float)dones[t * BATCH + b0 + tid];
        __syncthreads();

        // ===== phase 1: layer 0 =====
        // inA = mask * h0_prev   (full 256 cols for our 32 rows)
        for (int idx = tid; idx < RB * HID / 4; idx += R_THREADS) {
            int row = idx >> 6, k4 = idx & 63;
            float4 v = __ldcg((const float4*)&g_hbuf[rp][0][b0 + row][k4 * 4]);
            float m = smask[row];
            v.x *= m; v.y *= m; v.z *= m; v.w *= m;
            ((float4*)inA)[idx] = v;
        }
        __syncthreads();

        gemm_tile(inA, w0s, outA, b_hh0, hb, tid);   // gh0 tile
        __syncthreads();

        // gates layer 0: 32 rows x 16 hidden units
#pragma unroll
        for (int i = 0; i < 2; i++) {
            int e = tid + i * R_THREADS;           // 0..511
            int row = e >> 4, j = e & 15;
            size_t gbase = ((size_t)t * BATCH + b0 + row) * G3 + hb + j;
            float gi_r = g_gi0[gbase];
            float gi_z = g_gi0[gbase + 256];
            float gi_n = g_gi0[gbase + 512];
            float gh_r = outA[row * GSTRIDE + j];
            float gh_z = outA[row * GSTRIDE + 16 + j];
            float gh_n = outA[row * GSTRIDE + 32 + j];
            float r = sigmoidf_(gi_r + gh_r);
            float z = sigmoidf_(gi_z + gh_z);
            float n = tanhf(gi_n + r * gh_n);
            float hm = inA[row * HID + hb + j];    // already masked
            float hnew = (1.0f - z) * n + z * hm;
            __stcg(&g_hbuf[wp][0][b0 + row][hb + j], hnew);
        }

        // ---- single grid barrier per step (phase1 -> phase2) ----
        // Hazard matrix (all ordered by this barrier, transitively across steps):
        //  RAW  h0_new:   p1(t) writes hbuf[wp][0]  -> p2(t) reads      : this barrier
        //  RAW  h0_prev:  p1(t) writes hbuf[wp][0]  -> p1(t+1) reads    : this barrier(t)
        //  WAR  h0:       p1(t+1) writes hbuf[rp(t)][0] after all p1(t) reads, which
        //                 precede barrier(t); p1(t+1) follows barrier(t).
        //  WAR  h1:       p2(t+1) writes hbuf[rp(t)][1] after all p2(t) reads, which
        //                 precede barrier(t+1); p2(t+1) follows barrier(t+1).
        __syncthreads();
        if (tid == 0) {
            __threadfence();
            atomicAdd(&g_bar, 1u);
            unsigned target = (unsigned)(t + 1) * R_GRID;
            while (*((volatile unsigned*)&g_bar) < target) __nanosleep(32);
            __threadfence();
        }
        __syncthreads();

        // ===== phase 2: layer 1 =====
        // inA = h0_new (no mask), inB = mask * h1_prev
        for (int idx = tid; idx < RB * HID / 4; idx += R_THREADS) {
            int row = idx >> 6, k4 = idx & 63;
            float4 v = __ldcg((const float4*)&g_hbuf[wp][0][b0 + row][k4 * 4]);
            ((float4*)inA)[idx] = v;
            float4 u = __ldcg((const float4*)&g_hbuf[rp][1][b0 + row][k4 * 4]);
            float m = smask[row];
            u.x *= m; u.y *= m; u.z *= m; u.w *= m;
            ((float4*)inB)[idx] = u;
        }
        __syncthreads();

        gemm_tile(inA, w1s, outA, b_ih1, hb, tid);   // gi1 tile
        gemm_tile(inB, w2s, outB, b_hh1, hb, tid);   // gh1 tile
        __syncthreads();

#pragma unroll
        for (int i = 0; i < 2; i++) {
            int e = tid + i * R_THREADS;
            int row = e >> 4, j = e & 15;
            float gi_r = outA[row * GSTRIDE + j];
            float gi_z = outA[row * GSTRIDE + 16 + j];
            float gi_n = outA[row * GSTRIDE + 32 + j];
            float gh_r = outB[row * GSTRIDE + j];
            float gh_z = outB[row * GSTRIDE + 16 + j];
            float gh_n = outB[row * GSTRIDE + 32 + j];
            float r = sigmoidf_(gi_r + gh_r);
            float z = sigmoidf_(gi_z + gh_z);
            float n = tanhf(gi_n + r * gh_n);
            float hm = inB[row * HID + hb + j];     // masked h1_prev
            float hnew = (1.0f - z) * n + z * hm;
            __stcg(&g_hbuf[wp][1][b0 + row][hb + j], hnew);
            g_gruout[((size_t)t * BATCH + b0 + row) * HID + hb + j] = hnew;
        }
        __syncthreads();
    }
}

// ---------------- value head final reduction: v = hidden @ w_v2^T + b_v2 ----------------
__global__ void __launch_bounds__(256) vhead_kernel(
    const float* __restrict__ hidden, const float* __restrict__ w_v2,
    const float* __restrict__ b_v2, float* __restrict__ out)
{
    int row  = blockIdx.x * 8 + (threadIdx.x >> 5);
    int lane = threadIdx.x & 31;
    const float4* hp = (const float4*)(hidden + (size_t)row * HID);
    const float4* wp = (const float4*)w_v2;
    float s = 0.f;
#pragma unroll
    for (int i = 0; i < 2; i++) {
        float4 h4 = hp[lane * 2 + i];
        float4 w4 = __ldg(&wp[lane * 2 + i]);
        s += h4.x * w4.x + h4.y * w4.y + h4.z * w4.z + h4.w * w4.w;
    }
#pragma unroll
    for (int off = 16; off; off >>= 1) s += __shfl_xor_sync(0xffffffffu, s, off);
    if (lane == 0) out[row] = s + b_v2[0];
}

// ---------------- launch ----------------
extern "C" void kernel_launch(void* const* d_in, const int* in_sizes, int n_in,
                              void* d_out, int out_size) {
    const float* x        = (const float*)d_in[0];
    const int*   dones    = (const int*)  d_in[1];
    const float* h0       = (const float*)d_in[2];
    const float* w_shared = (const float*)d_in[3];
    const float* b_shared = (const float*)d_in[4];
    const float* w_ih     = (const float*)d_in[5];
    const float* w_hh     = (const float*)d_in[6];
    const float* b_ih     = (const float*)d_in[7];
    const float* b_hh     = (const float*)d_in[8];
    const float* w_v1     = (const float*)d_in[9];
    const float* b_v1     = (const float*)d_in[10];
    const float* w_v2     = (const float*)d_in[11];
    const float* b_v2     = (const float*)d_in[12];
    float* out = (float*)d_out;

    // idempotent, capture-safe (not a stream op); no static guard per harness rules
    cudaFuncSetAttribute(recurrent_kernel,
                         cudaFuncAttributeMaxDynamicSharedMemorySize, R_SMEM_BYTES);

    float* featsP;  cudaGetSymbolAddress((void**)&featsP,  g_feats);
    float* gi0P;    cudaGetSymbolAddress((void**)&gi0P,    g_gi0);
    float* gruoutP; cudaGetSymbolAddress((void**)&gruoutP, g_gruout);
    float* hiddenP = featsP;   // overlay: feats is dead after gi0 GEMM

    // reset barrier + seed h ping-pong (parity 0) with h0
    init_bar_kernel<<<1, 1>>>();
    cudaMemcpyToSymbolAsync(g_hbuf, h0, (size_t)2 * BATCH * HID * sizeof(float),
                            0, cudaMemcpyDeviceToDevice, 0);

    // feats = LReLU(x @ w_shared^T + b_shared)  [131072, 256]
    {
        dim3 g(HID / 64, ROWS_TOT / 64);
        gemm_lin_kernel<true><<<g, 128>>>(x, w_shared, b_shared, featsP,
                                          ROWS_TOT, HID, FIN);
    }
    // gi0 = feats @ w_ih0^T + b_ih0  [131072, 768]
    {
        dim3 g(G3 / 64, ROWS_TOT / 64);
        gemm_lin_kernel<false><<<g, 128>>>(featsP, w_ih, b_ih, gi0P,
                                           ROWS_TOT, G3, HID);
    }
    // sequential GRU rollout (persistent, grid-resident)
    recurrent_kernel<<<R_GRID, R_THREADS, R_SMEM_BYTES>>>(dones, w_ih, w_hh, b_ih, b_hh);

    // hidden = LReLU(gruout @ w_v1^T + b_v1)   (overwrites g_feats)
    {
        dim3 g(HID / 64, ROWS_TOT / 64);
        gemm_lin_kernel<true><<<g, 128>>>(gruoutP, w_v1, b_v1, hiddenP,
                                          ROWS_TOT, HID, HID);
    }
    // v = hidden @ w_v2^T + b_v2  -> out[0 : 131072)
    vhead_kernel<<<ROWS_TOT / 8, 256>>>(hiddenP, w_v2, b_v2, out);

    // h_final lives in parity 0 after 512 steps -> out[131072 : 262144)
    if (out_size >= 2 * ROWS_TOT) {
        cudaMemcpyFromSymbolAsync(out + ROWS_TOT, g_hbuf,
                                  (size_t)2 * BATCH * HID * sizeof(float),
                                  0, cudaMemcpyDeviceToDevice, 0);
    }
}

// round 7
// speedup vs baseline: 1.1281x; 1.1281x over previous
#include <cuda_runtime.h>
#include <math.h>

// ---------------- problem constants ----------------
#define T_STEPS 512
#define BATCH   256
#define FIN     64
#define HID     256
#define G3      768
#define ROWS_TOT (T_STEPS*BATCH)   // 131072

// recurrent kernel partitioning
#define R_GRID    128        // 8 batch tiles x 16 hidden tiles
#define R_THREADS 256
#define RB        32         // batch rows per CTA
#define WSTRIDE   256        // weight smem stride (broadcast-read: no pad needed)
#define INSTRIDE  260        // input-tile stride (pad: 16-lane float4 reads hit 2-phase floor)
#define GSTRIDE   49         // gate result tile stride

// dynamic smem floats: 3 weight slices + 2 input tiles + 2 gate tiles
#define R_SMEM_FLOATS (3*48*WSTRIDE + 2*RB*INSTRIDE + 2*RB*GSTRIDE)
#define R_SMEM_BYTES  (R_SMEM_FLOATS*4)

// ---------------- device scratch (static: no allocs allowed) ----------------
// g_feats doubles as the value-net hidden buffer (feats is dead after gi0).
__device__ float g_feats [(size_t)ROWS_TOT*HID];   // 134 MB (reused as v-hidden)
__device__ float g_gi0   [(size_t)ROWS_TOT*G3];    // 402 MB (layer0 gi incl b_ih0)
__device__ float g_gruout[(size_t)ROWS_TOT*HID];   // 134 MB
__device__ float g_hbuf  [2][2][BATCH][HID];       // [parity][layer][B][H] ping-pong
__device__ unsigned g_bar;

// ---------------- helpers ----------------
__device__ __forceinline__ float2 ffma2(float2 a, float2 b, float2 c) {
    unsigned long long au = *reinterpret_cast<unsigned long long*>(&a);
    unsigned long long bu = *reinterpret_cast<unsigned long long*>(&b);
    unsigned long long cu = *reinterpret_cast<unsigned long long*>(&c);
    unsigned long long du;
    asm("fma.rn.f32x2 %0, %1, %2, %3;" : "=l"(du) : "l"(au), "l"(bu), "l"(cu));
    return *reinterpret_cast<float2*>(&du);
}

__device__ __forceinline__ float sigmoidf_(float x) { return 1.0f / (1.0f + __expf(-x)); }

// local weight-row (0..47) -> global gate row for hidden base hb
__device__ __forceinline__ int grow_map(int hb, int c) {
    return (c < 16) ? (hb + c) : (c < 32) ? (256 + hb + (c - 16)) : (512 + hb + (c - 32));
}

__global__ void init_bar_kernel() { g_bar = 0u; }

// ---------------- generic tiled fp32 GEMM: C = act(A[M,K] @ W[N,K]^T + bias) ----------------
template <bool LRELU>
__global__ void __launch_bounds__(128) gemm_lin_kernel(
    const float* __restrict__ A, const float* __restrict__ W,
    const float* __restrict__ bias, float* __restrict__ C,
    int M, int N, int K)
{
    __shared__ __align__(16) float As[16][68];
    __shared__ __align__(16) float Bs[16][68];

    const int tid  = threadIdx.x;
    const int row0 = blockIdx.y * 64;
    const int col0 = blockIdx.x * 64;
    const int c0 = (tid & 15) * 4;   // 4 cols
    const int r0 = (tid >> 4) * 8;   // 8 rows

    float2 acc[4][4];
#pragma unroll
    for (int i = 0; i < 4; i++)
#pragma unroll
        for (int j = 0; j < 4; j++) acc[i][j] = make_float2(0.f, 0.f);

    for (int kt = 0; kt < K; kt += 16) {
#pragma unroll
        for (int i = 0; i < 2; i++) {
            int e  = tid + i * 128;         // 0..255
            int r  = e >> 2;                // 0..63
            int k4 = (e & 3) * 4;           // 0,4,8,12
            float4 va = *(const float4*)&A[(size_t)(row0 + r) * K + kt + k4];
            As[k4 + 0][r] = va.x; As[k4 + 1][r] = va.y; As[k4 + 2][r] = va.z; As[k4 + 3][r] = va.w;
            float4 vb = *(const float4*)&W[(size_t)(col0 + r) * K + kt + k4];
            Bs[k4 + 0][r] = vb.x; Bs[k4 + 1][r] = vb.y; Bs[k4 + 2][r] = vb.z; Bs[k4 + 3][r] = vb.w;
        }
        __syncthreads();
#pragma unroll
        for (int k = 0; k < 16; k++) {
            float4 a03 = *(const float4*)&As[k][r0];
            float4 a47 = *(const float4*)&As[k][r0 + 4];
            float4 b   = *(const float4*)&Bs[k][c0];
            float2 ap[4] = { make_float2(a03.x, a03.y), make_float2(a03.z, a03.w),
                             make_float2(a47.x, a47.y), make_float2(a47.z, a47.w) };
            float2 bd[4] = { make_float2(b.x, b.x), make_float2(b.y, b.y),
                             make_float2(b.z, b.z), make_float2(b.w, b.w) };
#pragma unroll
            for (int i = 0; i < 4; i++)
#pragma unroll
                for (int j = 0; j < 4; j++) acc[i][j] = ffma2(ap[i], bd[j], acc[i][j]);
        }
        __syncthreads();
    }

#pragma unroll
    for (int j = 0; j < 4; j++) {
        float bv = bias[col0 + c0 + j];
#pragma unroll
        for (int i = 0; i < 4; i++) {
            float v0 = acc[i][j].x + bv;
            float v1 = acc[i][j].y + bv;
            if (LRELU) { v0 = (v0 > 0.f) ? v0 : 0.01f * v0; v1 = (v1 > 0.f) ? v1 : 0.01f * v1; }
            C[(size_t)(row0 + r0 + 2 * i    ) * N + col0 + c0 + j] = v0;
            C[(size_t)(row0 + r0 + 2 * i + 1) * N + col0 + c0 + j] = v1;
        }
    }
}

// ---------------- recurrent tile GEMM: out[32][48] = in[32][256] @ w[48][256]^T + bias ----
// Layout: lanes 0..15 = 16 consecutive batch rows (thread covers rows rtl, rtl+16),
// warp-half selects col-group -> A loads coalesced LDS.128 (2-phase byte floor),
// weight loads broadcast LDS.128 (1 phase). 7 crossbar phases per 12 FFMA2.
__device__ __forceinline__ void gemm_tile(const float* __restrict__ in_s,
                                          const float* __restrict__ w_s,
                                          float* __restrict__ out_s,
                                          const float* __restrict__ bias_g,
                                          int hb, int tid)
{
    const int rtl = tid & 15;        // rows rtl, rtl+16
    const int ctl = tid >> 4;        // 0..15 -> cols 3*ctl..3*ctl+2
    const int c0  = ctl * 3;

    float2 a00 = make_float2(0.f, 0.f), a01 = a00, a02 = a00;
    float2 a10 = a00, a11 = a00, a12 = a00;

    const float* i0 = in_s + (size_t)rtl * INSTRIDE;
    const float* i1 = in_s + (size_t)(rtl + 16) * INSTRIDE;
    const float* w0 = w_s + (size_t)(c0 + 0) * WSTRIDE;
    const float* w1 = w_s + (size_t)(c0 + 1) * WSTRIDE;
    const float* w2 = w_s + (size_t)(c0 + 2) * WSTRIDE;

#pragma unroll 4
    for (int k = 0; k < HID; k += 4) {
        float4 x0 = *(const float4*)(i0 + k);
        float4 x1 = *(const float4*)(i1 + k);
        float4 b0 = *(const float4*)(w0 + k);
        float4 b1 = *(const float4*)(w1 + k);
        float4 b2 = *(const float4*)(w2 + k);
        float2 x0l = make_float2(x0.x, x0.y), x0h = make_float2(x0.z, x0.w);
        float2 x1l = make_float2(x1.x, x1.y), x1h = make_float2(x1.z, x1.w);
        float2 b0l = make_float2(b0.x, b0.y), b0h = make_float2(b0.z, b0.w);
        float2 b1l = make_float2(b1.x, b1.y), b1h = make_float2(b1.z, b1.w);
        float2 b2l = make_float2(b2.x, b2.y), b2h = make_float2(b2.z, b2.w);
        a00 = ffma2(x0l, b0l, a00); a00 = ffma2(x0h, b0h, a00);
        a01 = ffma2(x0l, b1l, a01); a01 = ffma2(x0h, b1h, a01);
        a02 = ffma2(x0l, b2l, a02); a02 = ffma2(x0h, b2h, a02);
        a10 = ffma2(x1l, b0l, a10); a10 = ffma2(x1h, b0h, a10);
        a11 = ffma2(x1l, b1l, a11); a11 = ffma2(x1h, b1h, a11);
        a12 = ffma2(x1l, b2l, a12); a12 = ffma2(x1h, b2h, a12);
    }
    float bb0 = __ldg(&bias_g[grow_map(hb, c0 + 0)]);
    float bb1 = __ldg(&bias_g[grow_map(hb, c0 + 1)]);
    float bb2 = __ldg(&bias_g[grow_map(hb, c0 + 2)]);
    out_s[(rtl     ) * GSTRIDE + c0 + 0] = a00.x + a00.y + bb0;
    out_s[(rtl     ) * GSTRIDE + c0 + 1] = a01.x + a01.y + bb1;
    out_s[(rtl     ) * GSTRIDE + c0 + 2] = a02.x + a02.y + bb2;
    out_s[(rtl + 16) * GSTRIDE + c0 + 0] = a10.x + a10.y + bb0;
    out_s[(rtl + 16) * GSTRIDE + c0 + 1] = a11.x + a11.y + bb1;
    out_s[(rtl + 16) * GSTRIDE + c0 + 2] = a12.x + a12.y + bb2;
}

// ---------------- persistent recurrent kernel ----------------
// blk = bt*16 + ct ; bt = batch tile (32 rows), ct = hidden tile (16 units -> 48 gate rows)
__global__ void __launch_bounds__(R_THREADS, 1) recurrent_kernel(
    const int*   __restrict__ dones,
    const float* __restrict__ w_ih,   // [2][768][256]
    const float* __restrict__ w_hh,   // [2][768][256]
    const float* __restrict__ b_ih,   // [2][768]
    const float* __restrict__ b_hh)   // [2][768]
{
    extern __shared__ __align__(16) float smem[];
    float* w0s = smem;                       // w_hh0 slice [48][WSTRIDE]
    float* w1s = w0s + 48 * WSTRIDE;         // w_ih1 slice
    float* w2s = w1s + 48 * WSTRIDE;         // w_hh1 slice
    float* inA = w2s + 48 * WSTRIDE;         // [32][INSTRIDE]
    float* inB = inA + RB * INSTRIDE;        // [32][INSTRIDE]
    float* outA = inB + RB * INSTRIDE;       // [32][GSTRIDE]
    float* outB = outA + RB * GSTRIDE;       // [32][GSTRIDE]
    __shared__ float smask[RB];

    const int tid = threadIdx.x;
    const int bt  = blockIdx.x >> 4;
    const int ct  = blockIdx.x & 15;
    const int b0  = bt * RB;
    const int hb  = ct * 16;

    const float* w_hh0 = w_hh;
    const float* w_ih1 = w_ih + 768 * 256;
    const float* w_hh1 = w_hh + 768 * 256;
    const float* b_hh0 = b_hh;
    const float* b_ih1 = b_ih + 768;
    const float* b_hh1 = b_hh + 768;

    // ---- load persistent weight slices (resident in smem for all 512 steps) ----
    for (int idx = tid; idx < 48 * (HID / 4); idx += R_THREADS) {
        int c = idx >> 6, k4 = idx & 63;
        int gr = grow_map(hb, c);
        *(float4*)&w0s[c * WSTRIDE + k4 * 4] = *(const float4*)&w_hh0[gr * HID + k4 * 4];
        *(float4*)&w1s[c * WSTRIDE + k4 * 4] = *(const float4*)&w_ih1[gr * HID + k4 * 4];
        *(float4*)&w2s[c * WSTRIDE + k4 * 4] = *(const float4*)&w_hh1[gr * HID + k4 * 4];
    }
    __syncthreads();

    // gate-unit mapping: thread handles e = tid and e = tid+256 -> (row = e>>4, j = e&15)
    const int grow0 = tid >> 4, gj0 = tid & 15;
    const int grow1 = (tid + 256) >> 4, gj1 = tid & 15;

    for (int t = 0; t < T_STEPS; t++) {
        const int rp = t & 1, wp = rp ^ 1;

        // ---- prefetch gi0 for this step's gates (DRAM, no reuse -> start early) ----
        size_t gb0 = ((size_t)t * BATCH + b0 + grow0) * G3 + hb + gj0;
        size_t gb1 = ((size_t)t * BATCH + b0 + grow1) * G3 + hb + gj1;
        float p_r0 = __ldcs(&g_gi0[gb0]);
        float p_z0 = __ldcs(&g_gi0[gb0 + 256]);
        float p_n0 = __ldcs(&g_gi0[gb0 + 512]);
        float p_r1 = __ldcs(&g_gi0[gb1]);
        float p_z1 = __ldcs(&g_gi0[gb1 + 256]);
        float p_n1 = __ldcs(&g_gi0[gb1 + 512]);

        // ---- done masks for this step ----
        if (tid < RB) smask[tid] = 1.0f - (float)dones[t * BATCH + b0 + tid];
        __syncthreads();

        // ===== phase 1: layer 0 =====
        // inA = mask * h0_prev   (full 256 cols for our 32 rows)
        for (int idx = tid; idx < RB * HID / 4; idx += R_THREADS) {
            int row = idx >> 6, k4 = idx & 63;
            float4 v = __ldcg((const float4*)&g_hbuf[rp][0][b0 + row][k4 * 4]);
            float m = smask[row];
            v.x *= m; v.y *= m; v.z *= m; v.w *= m;
            *(float4*)&inA[row * INSTRIDE + k4 * 4] = v;
        }
        __syncthreads();

        gemm_tile(inA, w0s, outA, b_hh0, hb, tid);   // gh0 tile
        __syncthreads();

        // gates layer 0: 32 rows x 16 hidden units (2 per thread, prefetched gi)
        {
            float gh_r = outA[grow0 * GSTRIDE + gj0];
            float gh_z = outA[grow0 * GSTRIDE + 16 + gj0];
            float gh_n = outA[grow0 * GSTRIDE + 32 + gj0];
            float r = sigmoidf_(p_r0 + gh_r);
            float z = sigmoidf_(p_z0 + gh_z);
            float n = tanhf(p_n0 + r * gh_n);
            float hm = inA[grow0 * INSTRIDE + hb + gj0];    // already masked
            __stcg(&g_hbuf[wp][0][b0 + grow0][hb + gj0], (1.0f - z) * n + z * hm);

            gh_r = outA[grow1 * GSTRIDE + gj1];
            gh_z = outA[grow1 * GSTRIDE + 16 + gj1];
            gh_n = outA[grow1 * GSTRIDE + 32 + gj1];
            r = sigmoidf_(p_r1 + gh_r);
            z = sigmoidf_(p_z1 + gh_z);
            n = tanhf(p_n1 + r * gh_n);
            hm = inA[grow1 * INSTRIDE + hb + gj1];
            __stcg(&g_hbuf[wp][0][b0 + grow1][hb + gj1], (1.0f - z) * n + z * hm);
        }

        // ---- single grid barrier per step (phase1 -> phase2) ----
        // All cross-step hazards are transitively ordered by this barrier (see R5 matrix).
        __syncthreads();
        if (tid == 0) {
            __threadfence();
            atomicAdd(&g_bar, 1u);
            unsigned target = (unsigned)(t + 1) * R_GRID;
            while (*((volatile unsigned*)&g_bar) < target) __nanosleep(32);
            __threadfence();
        }
        __syncthreads();

        // ===== phase 2: layer 1 =====
        // inA = h0_new (no mask), inB = mask * h1_prev
        for (int idx = tid; idx < RB * HID / 4; idx += R_THREADS) {
            int row = idx >> 6, k4 = idx & 63;
            float4 v = __ldcg((const float4*)&g_hbuf[wp][0][b0 + row][k4 * 4]);
            *(float4*)&inA[row * INSTRIDE + k4 * 4] = v;
            float4 u = __ldcg((const float4*)&g_hbuf[rp][1][b0 + row][k4 * 4]);
            float m = smask[row];
            u.x *= m; u.y *= m; u.z *= m; u.w *= m;
            *(float4*)&inB[row * INSTRIDE + k4 * 4] = u;
        }
        __syncthreads();

        gemm_tile(inA, w1s, outA, b_ih1, hb, tid);   // gi1 tile
        gemm_tile(inB, w2s, outB, b_hh1, hb, tid);   // gh1 tile
        __syncthreads();

#pragma unroll
        for (int i = 0; i < 2; i++) {
            int e = tid + i * R_THREADS;
            int row = e >> 4, j = e & 15;
            float gi_r = outA[row * GSTRIDE + j];
            float gi_z = outA[row * GSTRIDE + 16 + j];
            float gi_n = outA[row * GSTRIDE + 32 + j];
            float gh_r = outB[row * GSTRIDE + j];
            float gh_z = outB[row * GSTRIDE + 16 + j];
            float gh_n = outB[row * GSTRIDE + 32 + j];
            float r = sigmoidf_(gi_r + gh_r);
            float z = sigmoidf_(gi_z + gh_z);
            float n = tanhf(gi_n + r * gh_n);
            float hm = inB[row * INSTRIDE + hb + j];     // masked h1_prev
            float hnew = (1.0f - z) * n + z * hm;
            __stcg(&g_hbuf[wp][1][b0 + row][hb + j], hnew);
            g_gruout[((size_t)t * BATCH + b0 + row) * HID + hb + j] = hnew;
        }
        __syncthreads();
    }
}

// ---------------- value head final reduction: v = hidden @ w_v2^T + b_v2 ----------------
__global__ void __launch_bounds__(256) vhead_kernel(
    const float* __restrict__ hidden, const float* __restrict__ w_v2,
    const float* __restrict__ b_v2, float* __restrict__ out)
{
    int row  = blockIdx.x * 8 + (threadIdx.x >> 5);
    int lane = threadIdx.x & 31;
    const float4* hp = (const float4*)(hidden + (size_t)row * HID);
    const float4* wp = (const float4*)w_v2;
    float s = 0.f;
#pragma unroll
    for (int i = 0; i < 2; i++) {
        float4 h4 = hp[lane * 2 + i];
        float4 w4 = __ldg(&wp[lane * 2 + i]);
        s += h4.x * w4.x + h4.y * w4.y + h4.z * w4.z + h4.w * w4.w;
    }
#pragma unroll
    for (int off = 16; off; off >>= 1) s += __shfl_xor_sync(0xffffffffu, s, off);
    if (lane == 0) out[row] = s + b_v2[0];
}

// ---------------- launch ----------------
extern "C" void kernel_launch(void* const* d_in, const int* in_sizes, int n_in,
                              void* d_out, int out_size) {
    const float* x        = (const float*)d_in[0];
    const int*   dones    = (const int*)  d_in[1];
    const float* h0       = (const float*)d_in[2];
    const float* w_shared = (const float*)d_in[3];
    const float* b_shared = (const float*)d_in[4];
    const float* w_ih     = (const float*)d_in[5];
    const float* w_hh     = (const float*)d_in[6];
    const float* b_ih     = (const float*)d_in[7];
    const float* b_hh     = (const float*)d_in[8];
    const float* w_v1     = (const float*)d_in[9];
    const float* b_v1     = (const float*)d_in[10];
    const float* w_v2     = (const float*)d_in[11];
    const float* b_v2     = (const float*)d_in[12];
    float* out = (float*)d_out;

    // idempotent, capture-safe (not a stream op)
    cudaFuncSetAttribute(recurrent_kernel,
                         cudaFuncAttributeMaxDynamicSharedMemorySize, R_SMEM_BYTES);

    float* featsP;  cudaGetSymbolAddress((void**)&featsP,  g_feats);
    float* gi0P;    cudaGetSymbolAddress((void**)&gi0P,    g_gi0);
    float* gruoutP; cudaGetSymbolAddress((void**)&gruoutP, g_gruout);
    float* hiddenP = featsP;   // overlay: feats is dead after gi0 GEMM

    // reset barrier + seed h ping-pong (parity 0) with h0
    init_bar_kernel<<<1, 1>>>();
    cudaMemcpyToSymbolAsync(g_hbuf, h0, (size_t)2 * BATCH * HID * sizeof(float),
                            0, cudaMemcpyDeviceToDevice, 0);

    // feats = LReLU(x @ w_shared^T + b_shared)  [131072, 256]
    {
        dim3 g(HID / 64, ROWS_TOT / 64);
        gemm_lin_kernel<true><<<g, 128>>>(x, w_shared, b_shared, featsP,
                                          ROWS_TOT, HID, FIN);
    }
    // gi0 = feats @ w_ih0^T + b_ih0  [131072, 768]
    {
        dim3 g(G3 / 64, ROWS_TOT / 64);
        gemm_lin_kernel<false><<<g, 128>>>(featsP, w_ih, b_ih, gi0P,
                                           ROWS_TOT, G3, HID);
    }
    // sequential GRU rollout (persistent, grid-resident)
    recurrent_kernel<<<R_GRID, R_THREADS, R_SMEM_BYTES>>>(dones, w_ih, w_hh, b_ih, b_hh);

    // hidden = LReLU(gruout @ w_v1^T + b_v1)   (overwrites g_feats)
    {
        dim3 g(HID / 64, ROWS_TOT / 64);
        gemm_lin_kernel<true><<<g, 128>>>(gruoutP, w_v1, b_v1, hiddenP,
                                          ROWS_TOT, HID, HID);
    }
    // v = hidden @ w_v2^T + b_v2  -> out[0 : 131072)
    vhead_kernel<<<ROWS_TOT / 8, 256>>>(hiddenP, w_v2, b_v2, out);

    // h_final lives in parity 0 after 512 steps -> out[131072 : 262144)
    if (out_size >= 2 * ROWS_TOT) {
        cudaMemcpyFromSymbolAsync(out + ROWS_TOT, g_hbuf,
                                  (size_t)2 * BATCH * HID * sizeof(float),
                                  0, cudaMemcpyDeviceToDevice, 0);
    }
}